// round 14
// baseline (speedup 1.0000x reference)
#include <cuda_runtime.h>
#include <cstdint>

#define NN 100000
#define EE 1600000
#define EG 400000          // EE/4 (4 contiguous edges per 8-lane group)
#define DD 32
#define CUT_K 320000       // int(1600000 * 0.2)
#define EPS 1e-12f

// ---------------- scratch (static device globals; no allocation) ----------------
__device__ float     g_Y1[NN * DD];
__device__ float     g_Y2[NN * DD];
__device__ float     g_NH[NN * DD];   // L2-normalized rows of current hop input
__device__ float     g_scale[NN];     // hop2: norm^2 * max(||Y1 row||, eps)
__device__ unsigned  g_key[EE];       // monotone uint key of cosine
__device__ float     g_norm[NN];      // clip(deg,1)^-0.5
__device__ int       g_deg[NN];
__device__ unsigned  g_bins[4096];    // accumulation bins (256 used in pass 0)
__device__ unsigned  g_done = 0;      // last-block ticket
__device__ unsigned  g_prefix;        // selected threshold key (built over 3 passes)
__device__ unsigned  g_kremain;       // running rank / final #equal-keys to drop
__device__ unsigned  g_ticket;        // tie-break ticket counter

// monotone float -> uint key
__device__ __forceinline__ unsigned fkey(float f) {
    unsigned u = __float_as_uint(f);
    return (u & 0x80000000u) ? ~u : (u | 0x80000000u);
}

// gpu-scope acq_rel ticket (no CCTL.IVALL L1 flush, unlike __threadfence)
__device__ __forceinline__ unsigned ticket_acqrel(unsigned* p) {
    unsigned old;
    asm volatile("atom.add.acq_rel.gpu.global.u32 %0, [%1], %2;"
                 : "=r"(old) : "l"(p), "r"(1u) : "memory");
    return old;
}

__device__ __forceinline__ void red_add4(float* p, float4 a) {
    asm volatile("red.global.add.v4.f32 [%0], {%1, %2, %3, %4};"
                 :: "l"(p), "f"(a.x), "f"(a.y), "f"(a.z), "f"(a.w) : "memory");
}

// ---------------- kernels ----------------

// zero Y1 + Y2 + deg + bins + scalars (grid 3125 x 256)
__global__ void k_init() {
    int i = blockIdx.x * blockDim.x + threadIdx.x;
    ((float4*)g_Y1)[i] = make_float4(0.f, 0.f, 0.f, 0.f);
    ((float4*)g_Y2)[i] = make_float4(0.f, 0.f, 0.f, 0.f);
    if (i < NN) g_deg[i] = 0;
    if (i < 4096) g_bins[i] = 0;
    if (i == 0) { g_prefix = 0u; g_kremain = CUT_K; g_ticket = 0u; g_done = 0u; }
}

__global__ void k_deg(const int4* __restrict__ dst4) {
    int i = blockIdx.x * blockDim.x + threadIdx.x;
    if (i < EE / 4) {
        int4 d = dst4[i];
        atomicAdd(&g_deg[d.x], 1);
        atomicAdd(&g_deg[d.y], 1);
        atomicAdd(&g_deg[d.z], 1);
        atomicAdd(&g_deg[d.w], 1);
    }
}

// 8 lanes per node: NH = X / max(||X||,eps).
// DO_NORM: also compute deg-norm. DO_SCALE: scale = norm^2*len. RESET: re-arm selector.
template <int DO_NORM, int DO_SCALE, int RESET>
__global__ void k_prep(const float4* __restrict__ X4) {
    int gid  = blockIdx.x * blockDim.x + threadIdx.x;
    int node = gid >> 3;
    int sub  = gid & 7;
    float4 v = X4[node * 8 + sub];
    float s = v.x * v.x + v.y * v.y + v.z * v.z + v.w * v.w;
    s += __shfl_xor_sync(0xffffffffu, s, 1);
    s += __shfl_xor_sync(0xffffffffu, s, 2);
    s += __shfl_xor_sync(0xffffffffu, s, 4);   // all 8 lanes hold full sum
    float len  = fmaxf(sqrtf(s), EPS);
    float rinv = 1.0f / len;
    ((float4*)g_NH)[node * 8 + sub] =
        make_float4(v.x * rinv, v.y * rinv, v.z * rinv, v.w * rinv);
    if (sub == 0) {
        if (DO_NORM) {
            int d = g_deg[node];
            if (d < 1) d = 1;
            g_norm[node] = 1.0f / sqrtf((float)d);
        }
        if (DO_SCALE) {
            float nrm = g_norm[node];
            g_scale[node] = nrm * nrm * len;
        }
    }
    if (RESET && gid == 0) { g_prefix = 0u; g_kremain = CUT_K; g_ticket = 0u; }
}

// hop-1 cos: 8 lanes x 4 edges; keys + smem top-8 hist + last-block scan (no scatter)
__global__ void __launch_bounds__(256) k_cos(const int4* __restrict__ src4,
                                             const int4* __restrict__ dst4) {
    __shared__ unsigned sh[256];
    sh[threadIdx.x] = 0;
    __syncthreads();

    int gid = blockIdx.x * blockDim.x + threadIdx.x;
    int g   = gid >> 3;
    int sub = gid & 7;

    int4 S = __ldcg(&src4[g]);
    int4 D = __ldcg(&dst4[g]);
    const float4* NH4 = (const float4*)g_NH;

    float4 a0 = __ldcg(&NH4[S.x * 8 + sub]), b0 = __ldcg(&NH4[D.x * 8 + sub]);
    float4 a1 = __ldcg(&NH4[S.y * 8 + sub]), b1 = __ldcg(&NH4[D.y * 8 + sub]);
    float4 a2 = __ldcg(&NH4[S.z * 8 + sub]), b2 = __ldcg(&NH4[D.z * 8 + sub]);
    float4 a3 = __ldcg(&NH4[S.w * 8 + sub]), b3 = __ldcg(&NH4[D.w * 8 + sub]);

    float p0 = a0.x * b0.x + a0.y * b0.y + a0.z * b0.z + a0.w * b0.w;
    float p1 = a1.x * b1.x + a1.y * b1.y + a1.z * b1.z + a1.w * b1.w;
    float p2 = a2.x * b2.x + a2.y * b2.y + a2.z * b2.z + a2.w * b2.w;
    float p3 = a3.x * b3.x + a3.y * b3.y + a3.z * b3.z + a3.w * b3.w;
    #pragma unroll
    for (int off = 1; off < 8; off <<= 1) {
        p0 += __shfl_xor_sync(0xffffffffu, p0, off);
        p1 += __shfl_xor_sync(0xffffffffu, p1, off);
        p2 += __shfl_xor_sync(0xffffffffu, p2, off);
        p3 += __shfl_xor_sync(0xffffffffu, p3, off);
    }
    if (sub == 0) {
        uint4 k;
        k.x = fkey(p0); k.y = fkey(p1); k.z = fkey(p2); k.w = fkey(p3);
        ((uint4*)g_key)[g] = k;
        atomicAdd(&sh[k.x >> 24], 1u);
        atomicAdd(&sh[k.y >> 24], 1u);
        atomicAdd(&sh[k.z >> 24], 1u);
        atomicAdd(&sh[k.w >> 24], 1u);
    }
    __syncthreads();
    unsigned c = sh[threadIdx.x];
    if (c) atomicAdd(&g_bins[threadIdx.x], c);
    __syncthreads();

    int last = 0;
    if (threadIdx.x == 0) last = (ticket_acqrel(&g_done) == gridDim.x - 1);
    last = __syncthreads_or(last);
    if (!last) return;

    int t = threadIdx.x;
    unsigned cnt = g_bins[t];
    sh[t] = cnt;
    __syncthreads();
    #pragma unroll
    for (int off = 1; off < 256; off <<= 1) {
        unsigned v = (t >= off) ? sh[t - off] : 0u;
        __syncthreads();
        sh[t] += v;
        __syncthreads();
    }
    unsigned incl = sh[t];
    unsigned excl = incl - cnt;
    unsigned kr = g_kremain;
    if (excl < kr && incl >= kr) {
        g_prefix = ((unsigned)t) << 24;
        g_kremain = kr - excl;
    }
    g_bins[t] = 0;
    if (t == 0) g_done = 0;
}

// hop-2 fused cos: same as k_cos but also REDs the full (unpruned) message
// NH[src]*scale[src] into Y (corr subtracts the pruned 20% later).
// Safe: Y2 feeds only the GEMM, so add-then-subtract rounding (~1e-7) cannot
// flip any selection.
__global__ void __launch_bounds__(256) k_cosF(const int4* __restrict__ src4,
                                              const int4* __restrict__ dst4,
                                              float* __restrict__ Y) {
    __shared__ unsigned sh[256];
    sh[threadIdx.x] = 0;
    __syncthreads();

    int gid = blockIdx.x * blockDim.x + threadIdx.x;
    int g   = gid >> 3;
    int sub = gid & 7;

    int4 S = __ldcg(&src4[g]);
    int4 D = __ldcg(&dst4[g]);
    const float4* NH4 = (const float4*)g_NH;

    float4 a0 = __ldcg(&NH4[S.x * 8 + sub]), b0 = __ldcg(&NH4[D.x * 8 + sub]);
    float4 a1 = __ldcg(&NH4[S.y * 8 + sub]), b1 = __ldcg(&NH4[D.y * 8 + sub]);
    float4 a2 = __ldcg(&NH4[S.z * 8 + sub]), b2 = __ldcg(&NH4[D.z * 8 + sub]);
    float4 a3 = __ldcg(&NH4[S.w * 8 + sub]), b3 = __ldcg(&NH4[D.w * 8 + sub]);
    float c0 = g_scale[S.x], c1 = g_scale[S.y], c2 = g_scale[S.z], c3 = g_scale[S.w];

    red_add4(Y + D.x * DD + sub * 4, make_float4(a0.x * c0, a0.y * c0, a0.z * c0, a0.w * c0));
    red_add4(Y + D.y * DD + sub * 4, make_float4(a1.x * c1, a1.y * c1, a1.z * c1, a1.w * c1));
    red_add4(Y + D.z * DD + sub * 4, make_float4(a2.x * c2, a2.y * c2, a2.z * c2, a2.w * c2));
    red_add4(Y + D.w * DD + sub * 4, make_float4(a3.x * c3, a3.y * c3, a3.z * c3, a3.w * c3));

    float p0 = a0.x * b0.x + a0.y * b0.y + a0.z * b0.z + a0.w * b0.w;
    float p1 = a1.x * b1.x + a1.y * b1.y + a1.z * b1.z + a1.w * b1.w;
    float p2 = a2.x * b2.x + a2.y * b2.y + a2.z * b2.z + a2.w * b2.w;
    float p3 = a3.x * b3.x + a3.y * b3.y + a3.z * b3.z + a3.w * b3.w;
    #pragma unroll
    for (int off = 1; off < 8; off <<= 1) {
        p0 += __shfl_xor_sync(0xffffffffu, p0, off);
        p1 += __shfl_xor_sync(0xffffffffu, p1, off);
        p2 += __shfl_xor_sync(0xffffffffu, p2, off);
        p3 += __shfl_xor_sync(0xffffffffu, p3, off);
    }
    if (sub == 0) {
        uint4 k;
        k.x = fkey(p0); k.y = fkey(p1); k.z = fkey(p2); k.w = fkey(p3);
        ((uint4*)g_key)[g] = k;
        atomicAdd(&sh[k.x >> 24], 1u);
        atomicAdd(&sh[k.y >> 24], 1u);
        atomicAdd(&sh[k.z >> 24], 1u);
        atomicAdd(&sh[k.w >> 24], 1u);
    }
    __syncthreads();
    unsigned c = sh[threadIdx.x];
    if (c) atomicAdd(&g_bins[threadIdx.x], c);
    __syncthreads();

    int last = 0;
    if (threadIdx.x == 0) last = (ticket_acqrel(&g_done) == gridDim.x - 1);
    last = __syncthreads_or(last);
    if (!last) return;

    int t = threadIdx.x;
    unsigned cnt = g_bins[t];
    sh[t] = cnt;
    __syncthreads();
    #pragma unroll
    for (int off = 1; off < 256; off <<= 1) {
        unsigned v = (t >= off) ? sh[t - off] : 0u;
        __syncthreads();
        sh[t] += v;
        __syncthreads();
    }
    unsigned incl = sh[t];
    unsigned excl = incl - cnt;
    unsigned kr = g_kremain;
    if (excl < kr && incl >= kr) {
        g_prefix = ((unsigned)t) << 24;
        g_kremain = kr - excl;
    }
    g_bins[t] = 0;
    if (t == 0) g_done = 0;
}

// 12-bit radix pass (SHIFT=12 then 0): smem 4096-bin hist + last-block scan
template <int SHIFT>
__global__ void __launch_bounds__(256) k_hs12() {
    __shared__ unsigned sh[4096];
    int t = threadIdx.x;
    #pragma unroll
    for (int i = 0; i < 16; i++) sh[t + i * 256] = 0;
    __syncthreads();

    unsigned hi = g_prefix >> (SHIFT + 12);
    int stride = gridDim.x * blockDim.x;
    for (int i = blockIdx.x * blockDim.x + t; i < EE / 4; i += stride) {
        uint4 k = __ldcg(&((const uint4*)g_key)[i]);
        if ((k.x >> (SHIFT + 12)) == hi) atomicAdd(&sh[(k.x >> SHIFT) & 0xFFFu], 1u);
        if ((k.y >> (SHIFT + 12)) == hi) atomicAdd(&sh[(k.y >> SHIFT) & 0xFFFu], 1u);
        if ((k.z >> (SHIFT + 12)) == hi) atomicAdd(&sh[(k.z >> SHIFT) & 0xFFFu], 1u);
        if ((k.w >> (SHIFT + 12)) == hi) atomicAdd(&sh[(k.w >> SHIFT) & 0xFFFu], 1u);
    }
    __syncthreads();
    #pragma unroll
    for (int i = 0; i < 16; i++) {
        unsigned c = sh[t + i * 256];
        if (c) atomicAdd(&g_bins[t + i * 256], c);
    }
    __syncthreads();

    int last = 0;
    if (t == 0) last = (ticket_acqrel(&g_done) == gridDim.x - 1);
    last = __syncthreads_or(last);
    if (!last) return;

    unsigned mysum = 0;
    unsigned local[16];
    #pragma unroll
    for (int i = 0; i < 16; i++) { local[i] = g_bins[t * 16 + i]; mysum += local[i]; }
    sh[t] = mysum;
    __syncthreads();
    #pragma unroll
    for (int off = 1; off < 256; off <<= 1) {
        unsigned v = (t >= off) ? sh[t - off] : 0u;
        __syncthreads();
        sh[t] += v;
        __syncthreads();
    }
    unsigned incl = sh[t];
    unsigned excl = incl - mysum;
    unsigned kr = g_kremain;
    if (excl < kr && incl >= kr) {
        unsigned run = excl;
        #pragma unroll
        for (int i = 0; i < 16; i++) {
            if (run + local[i] >= kr) {
                g_prefix |= ((unsigned)(t * 16 + i)) << SHIFT;
                g_kremain = kr - run;
                break;
            }
            run += local[i];
        }
    }
    #pragma unroll
    for (int i = 0; i < 16; i++) g_bins[t * 16 + i] = 0;
    if (t == 0) g_done = 0;
}

// hop-1 kept-only scatter: messages X[src]*norm[src], EXACT reference arithmetic
// (Y1 feeds hop-2's selection, so no add-then-subtract here).
__global__ void __launch_bounds__(256) k_scatter(const float4* __restrict__ X4,
                                                 float* __restrict__ Y,
                                                 const int4* __restrict__ src4,
                                                 const int4* __restrict__ dst4) {
    int gid = blockIdx.x * blockDim.x + threadIdx.x;
    int g   = gid >> 3;
    int sub = gid & 7;
    int lane   = threadIdx.x & 31;
    int leader = lane & 24;

    unsigned kp = 0;
    if (sub == 0) {
        unsigned T = g_prefix;
        unsigned need_eq = g_kremain;
        uint4 k = __ldcg(&((const uint4*)g_key)[g]);
        unsigned u[4] = {k.x, k.y, k.z, k.w};
        #pragma unroll
        for (int j = 0; j < 4; j++) {
            if (u[j] > T) kp |= (1u << j);
            else if (u[j] == T && atomicAdd(&g_ticket, 1u) >= need_eq) kp |= (1u << j);
        }
    }
    kp = __shfl_sync(0xffffffffu, kp, leader);
    if (kp == 0) return;

    int4 S = __ldcg(&src4[g]);
    int4 D = __ldcg(&dst4[g]);
    int s[4] = {S.x, S.y, S.z, S.w};
    int d[4] = {D.x, D.y, D.z, D.w};

    #pragma unroll
    for (int j = 0; j < 4; j++) {
        if (kp & (1u << j)) {
            float ns = g_norm[s[j]];
            float4 a = __ldcg(&X4[s[j] * 8 + sub]);
            a.x *= ns; a.y *= ns; a.z *= ns; a.w *= ns;
            red_add4(Y + d[j] * DD + sub * 4, a);
        }
    }
}

// hop-2 correction: subtract pruned (bottom CUT_K) messages from Y.
__global__ void __launch_bounds__(256) k_corr(float* __restrict__ Y,
                                              const int4* __restrict__ src4,
                                              const int4* __restrict__ dst4) {
    int gid = blockIdx.x * blockDim.x + threadIdx.x;
    int g   = gid >> 3;
    int sub = gid & 7;
    int lane   = threadIdx.x & 31;
    int leader = lane & 24;

    unsigned kp = 0;
    if (sub == 0) {
        unsigned T = g_prefix;
        unsigned need_eq = g_kremain;
        uint4 k = __ldcg(&((const uint4*)g_key)[g]);
        unsigned u[4] = {k.x, k.y, k.z, k.w};
        #pragma unroll
        for (int j = 0; j < 4; j++) {
            if (u[j] < T) kp |= (1u << j);
            else if (u[j] == T && atomicAdd(&g_ticket, 1u) < need_eq) kp |= (1u << j);
        }
    }
    kp = __shfl_sync(0xffffffffu, kp, leader);
    if (kp == 0) return;

    int4 S = __ldcg(&src4[g]);
    int4 D = __ldcg(&dst4[g]);
    int s[4] = {S.x, S.y, S.z, S.w};
    int d[4] = {D.x, D.y, D.z, D.w};
    const float4* NH4 = (const float4*)g_NH;

    #pragma unroll
    for (int j = 0; j < 4; j++) {
        if (kp & (1u << j)) {
            float c = -g_scale[s[j]];           // negate: subtract the message
            float4 a = __ldcg(&NH4[s[j] * 8 + sub]);
            red_add4(Y + d[j] * DD + sub * 4,
                     make_float4(a.x * c, a.y * c, a.z * c, a.w * c));
        }
    }
}

// out[i,:] = (Y2[i,:] * norm[i]) @ W^T    W is [32,32] row-major
__global__ void k_fc(const float4* __restrict__ Y4, const float* __restrict__ W,
                     float* __restrict__ out) {
    __shared__ float sW[DD * DD];
    int t = threadIdx.x;
    #pragma unroll
    for (int i = 0; i < 4; i++) sW[t + i * 256] = W[t + i * 256];
    __syncthreads();

    int node = blockIdx.x * blockDim.x + t;
    if (node >= NN) return;
    float nrm = g_norm[node];
    float y[DD];
    #pragma unroll
    for (int j = 0; j < 8; j++) {
        float4 v = Y4[node * 8 + j];
        y[j * 4 + 0] = v.x * nrm;
        y[j * 4 + 1] = v.y * nrm;
        y[j * 4 + 2] = v.z * nrm;
        y[j * 4 + 3] = v.w * nrm;
    }
    #pragma unroll
    for (int o = 0; o < DD; o += 4) {
        float4 acc = make_float4(0.f, 0.f, 0.f, 0.f);
        #pragma unroll
        for (int k = 0; k < DD; k++) {
            float yk = y[k];
            acc.x += yk * sW[(o + 0) * DD + k];
            acc.y += yk * sW[(o + 1) * DD + k];
            acc.z += yk * sW[(o + 2) * DD + k];
            acc.w += yk * sW[(o + 3) * DD + k];
        }
        *reinterpret_cast<float4*>(out + node * DD + o) = acc;
    }
}

// ---------------- launch ----------------

extern "C" void kernel_launch(void* const* d_in, const int* in_sizes, int n_in,
                              void* d_out, int out_size) {
    const float* F   = (const float*)d_in[0];
    const float* W   = (const float*)d_in[1];
    const int*   src = (const int*)d_in[2];
    const int*   dst = (const int*)d_in[3];
    float* out = (float*)d_out;

    const float4* F4  = (const float4*)F;
    const int4* src4  = (const int4*)src;
    const int4* dst4  = (const int4*)dst;

    void* p1; void* p2;
    cudaGetSymbolAddress(&p1, g_Y1);
    cudaGetSymbolAddress(&p2, g_Y2);
    float* Y1 = (float*)p1;
    float* Y2 = (float*)p2;

    const int TB = 256;
    const int gridN  = (NN + TB - 1) / TB;     // 391
    const int gridN8 = (NN * 8) / TB;          // 3125 (exact)
    const int gridE4 = (EG * 8) / TB;          // 12500 (exact)
    const int gridV4 = (EE / 4 + TB - 1) / TB; // 1563
    const int gridHS = 1184;

    k_init<<<gridN8, TB>>>();
    k_deg<<<gridV4, TB>>>(dst4);

    // ---- hop 1 (exact messages; Y1 feeds hop-2 selection) ----
    k_prep<1, 0, 0><<<gridN8, TB>>>(F4);       // NH(F) + deg-norm
    k_cos<<<gridE4, TB>>>(src4, dst4);         // keys + pass0 hist + scan
    k_hs12<12><<<gridHS, TB>>>();              // bits [12:24)
    k_hs12<0><<<gridHS, TB>>>();               // bits [0:12)
    k_scatter<<<gridE4, TB>>>(F4, Y1, src4, dst4);  // kept-only, msg = F*norm

    // ---- hop 2 (fused add-all + subtract-pruned; Y2 only feeds GEMM) ----
    k_prep<0, 1, 1><<<gridN8, TB>>>((const float4*)Y1);  // NH(Y1), scale=norm^2*len, re-arm
    k_cosF<<<gridE4, TB>>>(src4, dst4, Y2);    // keys + hist + scan + RED-all
    k_hs12<12><<<gridHS, TB>>>();
    k_hs12<0><<<gridHS, TB>>>();
    k_corr<<<gridE4, TB>>>(Y2, src4, dst4);    // subtract pruned 20%

    // ---- final: out = (Y2 * norm) @ W^T ----
    k_fc<<<gridN, TB>>>((const float4*)Y2, W, out);
}

// round 15
// speedup vs baseline: 1.0442x; 1.0442x over previous
#include <cuda_runtime.h>
#include <cstdint>

#define NN 100000
#define EE 1600000
#define EG 400000          // EE/4 (4 contiguous edges per 8-lane group)
#define DD 32
#define CUT_K 320000       // int(1600000 * 0.2)
#define EPS 1e-12f

// ---------------- scratch (static device globals; no allocation) ----------------
__device__ float     g_Y1[NN * DD];
__device__ float     g_Y2[NN * DD];
__device__ float     g_NH[NN * DD];   // L2-normalized rows of current hop state
__device__ float     g_XS[NN * DD];   // pre-scaled message rows: h * norm
__device__ unsigned  g_key[EE];       // monotone uint key of cosine
__device__ float     g_norm[NN];      // clip(deg,1)^-0.5
__device__ int       g_deg[NN];
__device__ unsigned  g_bins[4096];    // accumulation bins (256 used in pass 0)
__device__ unsigned  g_done = 0;      // last-block ticket
__device__ unsigned  g_prefix;        // selected threshold key (built over 3 passes)
__device__ unsigned  g_kremain;       // running rank / final #equal-keys to drop
__device__ unsigned  g_ticket;        // tie-break ticket counter

// monotone float -> uint key
__device__ __forceinline__ unsigned fkey(float f) {
    unsigned u = __float_as_uint(f);
    return (u & 0x80000000u) ? ~u : (u | 0x80000000u);
}

// gpu-scope acq_rel ticket (no CCTL.IVALL L1 flush, unlike __threadfence)
__device__ __forceinline__ unsigned ticket_acqrel(unsigned* p) {
    unsigned old;
    asm volatile("atom.add.acq_rel.gpu.global.u32 %0, [%1], %2;"
                 : "=r"(old) : "l"(p), "r"(1u) : "memory");
    return old;
}

__device__ __forceinline__ void red_add4(float* p, float4 a) {
    asm volatile("red.global.add.v4.f32 [%0], {%1, %2, %3, %4};"
                 :: "l"(p), "f"(a.x), "f"(a.y), "f"(a.z), "f"(a.w) : "memory");
}

// ---------------- kernels ----------------

// zero Y1 + Y2 + deg + bins + scalars (grid 3125 x 256)
__global__ void k_init() {
    int i = blockIdx.x * blockDim.x + threadIdx.x;
    ((float4*)g_Y1)[i] = make_float4(0.f, 0.f, 0.f, 0.f);
    ((float4*)g_Y2)[i] = make_float4(0.f, 0.f, 0.f, 0.f);
    if (i < NN) g_deg[i] = 0;
    if (i < 4096) g_bins[i] = 0;
    if (i == 0) { g_prefix = 0u; g_kremain = CUT_K; g_ticket = 0u; g_done = 0u; }
}

__global__ void k_deg(const int4* __restrict__ dst4) {
    int i = blockIdx.x * blockDim.x + threadIdx.x;
    if (i < EE / 4) {
        int4 d = dst4[i];
        atomicAdd(&g_deg[d.x], 1);
        atomicAdd(&g_deg[d.y], 1);
        atomicAdd(&g_deg[d.z], 1);
        atomicAdd(&g_deg[d.w], 1);
    }
}

// hop-1 prep (8 lanes/node): reads F.
//   norm = clip(deg,1)^-0.5 (stored)
//   NH   = F / max(||F||, eps)           (reference normalize(F))
//   XS   = F * norm                      (reference h*norm message rows, exact)
__global__ void k_prep1(const float4* __restrict__ X4) {
    int gid  = blockIdx.x * blockDim.x + threadIdx.x;
    int node = gid >> 3;
    int sub  = gid & 7;
    float4 v = X4[node * 8 + sub];
    float s = v.x * v.x + v.y * v.y + v.z * v.z + v.w * v.w;
    s += __shfl_xor_sync(0xffffffffu, s, 1);
    s += __shfl_xor_sync(0xffffffffu, s, 2);
    s += __shfl_xor_sync(0xffffffffu, s, 4);   // all 8 lanes hold full sum
    float rinv = 1.0f / fmaxf(sqrtf(s), EPS);
    int d = g_deg[node];
    if (d < 1) d = 1;
    float nrm = 1.0f / sqrtf((float)d);
    ((float4*)g_NH)[node * 8 + sub] =
        make_float4(v.x * rinv, v.y * rinv, v.z * rinv, v.w * rinv);
    ((float4*)g_XS)[node * 8 + sub] =
        make_float4(v.x * nrm, v.y * nrm, v.z * nrm, v.w * nrm);
    if (sub == 0) g_norm[node] = nrm;
}

// hop-2 prep (8 lanes/node): reads Y1, forms H2 = Y1*norm FIRST (reference
// rounding), then NH = H2/max(||H2||,eps) and XS = H2*norm. Re-arms selector.
__global__ void k_prep2(const float4* __restrict__ Y4) {
    int gid  = blockIdx.x * blockDim.x + threadIdx.x;
    int node = gid >> 3;
    int sub  = gid & 7;
    float4 v = Y4[node * 8 + sub];
    float nrm = g_norm[node];
    v.x *= nrm; v.y *= nrm; v.z *= nrm; v.w *= nrm;   // H2 row
    float s = v.x * v.x + v.y * v.y + v.z * v.z + v.w * v.w;
    s += __shfl_xor_sync(0xffffffffu, s, 1);
    s += __shfl_xor_sync(0xffffffffu, s, 2);
    s += __shfl_xor_sync(0xffffffffu, s, 4);
    float rinv = 1.0f / fmaxf(sqrtf(s), EPS);
    ((float4*)g_NH)[node * 8 + sub] =
        make_float4(v.x * rinv, v.y * rinv, v.z * rinv, v.w * rinv);
    ((float4*)g_XS)[node * 8 + sub] =
        make_float4(v.x * nrm, v.y * nrm, v.z * nrm, v.w * nrm);
    if (gid == 0) { g_prefix = 0u; g_kremain = CUT_K; g_ticket = 0u; }
}

// cos: 8 lanes x 4 contiguous edges per group; keys + smem top-8 hist +
// last-block scan (sets g_prefix bits [24:32))
__global__ void __launch_bounds__(256) k_cos(const int4* __restrict__ src4,
                                             const int4* __restrict__ dst4) {
    __shared__ unsigned sh[256];
    sh[threadIdx.x] = 0;
    __syncthreads();

    int gid = blockIdx.x * blockDim.x + threadIdx.x;
    int g   = gid >> 3;
    int sub = gid & 7;

    int4 S = __ldcg(&src4[g]);
    int4 D = __ldcg(&dst4[g]);
    const float4* NH4 = (const float4*)g_NH;

    float4 a0 = __ldcg(&NH4[S.x * 8 + sub]), b0 = __ldcg(&NH4[D.x * 8 + sub]);
    float4 a1 = __ldcg(&NH4[S.y * 8 + sub]), b1 = __ldcg(&NH4[D.y * 8 + sub]);
    float4 a2 = __ldcg(&NH4[S.z * 8 + sub]), b2 = __ldcg(&NH4[D.z * 8 + sub]);
    float4 a3 = __ldcg(&NH4[S.w * 8 + sub]), b3 = __ldcg(&NH4[D.w * 8 + sub]);

    float p0 = a0.x * b0.x + a0.y * b0.y + a0.z * b0.z + a0.w * b0.w;
    float p1 = a1.x * b1.x + a1.y * b1.y + a1.z * b1.z + a1.w * b1.w;
    float p2 = a2.x * b2.x + a2.y * b2.y + a2.z * b2.z + a2.w * b2.w;
    float p3 = a3.x * b3.x + a3.y * b3.y + a3.z * b3.z + a3.w * b3.w;
    #pragma unroll
    for (int off = 1; off < 8; off <<= 1) {
        p0 += __shfl_xor_sync(0xffffffffu, p0, off);
        p1 += __shfl_xor_sync(0xffffffffu, p1, off);
        p2 += __shfl_xor_sync(0xffffffffu, p2, off);
        p3 += __shfl_xor_sync(0xffffffffu, p3, off);
    }
    if (sub == 0) {
        uint4 k;
        k.x = fkey(p0); k.y = fkey(p1); k.z = fkey(p2); k.w = fkey(p3);
        ((uint4*)g_key)[g] = k;
        atomicAdd(&sh[k.x >> 24], 1u);
        atomicAdd(&sh[k.y >> 24], 1u);
        atomicAdd(&sh[k.z >> 24], 1u);
        atomicAdd(&sh[k.w >> 24], 1u);
    }
    __syncthreads();
    unsigned c = sh[threadIdx.x];
    if (c) atomicAdd(&g_bins[threadIdx.x], c);
    __syncthreads();

    int last = 0;
    if (threadIdx.x == 0) last = (ticket_acqrel(&g_done) == gridDim.x - 1);
    last = __syncthreads_or(last);
    if (!last) return;

    int t = threadIdx.x;
    unsigned cnt = g_bins[t];
    sh[t] = cnt;
    __syncthreads();
    #pragma unroll
    for (int off = 1; off < 256; off <<= 1) {
        unsigned v = (t >= off) ? sh[t - off] : 0u;
        __syncthreads();
        sh[t] += v;
        __syncthreads();
    }
    unsigned incl = sh[t];
    unsigned excl = incl - cnt;
    unsigned kr = g_kremain;
    if (excl < kr && incl >= kr) {
        g_prefix = ((unsigned)t) << 24;
        g_kremain = kr - excl;
    }
    g_bins[t] = 0;
    if (t == 0) g_done = 0;
}

// 12-bit radix pass (SHIFT=12 then 0): smem 4096-bin hist + last-block scan
template <int SHIFT>
__global__ void __launch_bounds__(256) k_hs12() {
    __shared__ unsigned sh[4096];
    int t = threadIdx.x;
    #pragma unroll
    for (int i = 0; i < 16; i++) sh[t + i * 256] = 0;
    __syncthreads();

    unsigned hi = g_prefix >> (SHIFT + 12);
    int stride = gridDim.x * blockDim.x;
    for (int i = blockIdx.x * blockDim.x + t; i < EE / 4; i += stride) {
        uint4 k = __ldcg(&((const uint4*)g_key)[i]);
        if ((k.x >> (SHIFT + 12)) == hi) atomicAdd(&sh[(k.x >> SHIFT) & 0xFFFu], 1u);
        if ((k.y >> (SHIFT + 12)) == hi) atomicAdd(&sh[(k.y >> SHIFT) & 0xFFFu], 1u);
        if ((k.z >> (SHIFT + 12)) == hi) atomicAdd(&sh[(k.z >> SHIFT) & 0xFFFu], 1u);
        if ((k.w >> (SHIFT + 12)) == hi) atomicAdd(&sh[(k.w >> SHIFT) & 0xFFFu], 1u);
    }
    __syncthreads();
    #pragma unroll
    for (int i = 0; i < 16; i++) {
        unsigned c = sh[t + i * 256];
        if (c) atomicAdd(&g_bins[t + i * 256], c);
    }
    __syncthreads();

    int last = 0;
    if (t == 0) last = (ticket_acqrel(&g_done) == gridDim.x - 1);
    last = __syncthreads_or(last);
    if (!last) return;

    unsigned mysum = 0;
    unsigned local[16];
    #pragma unroll
    for (int i = 0; i < 16; i++) { local[i] = g_bins[t * 16 + i]; mysum += local[i]; }
    sh[t] = mysum;
    __syncthreads();
    #pragma unroll
    for (int off = 1; off < 256; off <<= 1) {
        unsigned v = (t >= off) ? sh[t - off] : 0u;
        __syncthreads();
        sh[t] += v;
        __syncthreads();
    }
    unsigned incl = sh[t];
    unsigned excl = incl - mysum;
    unsigned kr = g_kremain;
    if (excl < kr && incl >= kr) {
        unsigned run = excl;
        #pragma unroll
        for (int i = 0; i < 16; i++) {
            if (run + local[i] >= kr) {
                g_prefix |= ((unsigned)(t * 16 + i)) << SHIFT;
                g_kremain = kr - run;
                break;
            }
            run += local[i];
        }
    }
    #pragma unroll
    for (int i = 0; i < 16; i++) g_bins[t * 16 + i] = 0;
    if (t == 0) g_done = 0;
}

// kept-only scatter: gathers pre-scaled XS[src] rows and REDs into Y.
// No per-edge norm lookup (folded into XS at prep time, reference-exact).
__global__ void __launch_bounds__(256) k_scatter(float* __restrict__ Y,
                                                 const int4* __restrict__ src4,
                                                 const int4* __restrict__ dst4) {
    int gid = blockIdx.x * blockDim.x + threadIdx.x;
    int g   = gid >> 3;
    int sub = gid & 7;
    int lane   = threadIdx.x & 31;
    int leader = lane & 24;

    unsigned kp = 0;
    if (sub == 0) {
        unsigned T = g_prefix;
        unsigned need_eq = g_kremain;
        uint4 k = __ldcg(&((const uint4*)g_key)[g]);
        unsigned u[4] = {k.x, k.y, k.z, k.w};
        #pragma unroll
        for (int j = 0; j < 4; j++) {
            if (u[j] > T) kp |= (1u << j);
            else if (u[j] == T && atomicAdd(&g_ticket, 1u) >= need_eq) kp |= (1u << j);
        }
    }
    kp = __shfl_sync(0xffffffffu, kp, leader);
    if (kp == 0) return;

    int4 S = __ldcg(&src4[g]);
    int4 D = __ldcg(&dst4[g]);
    int s[4] = {S.x, S.y, S.z, S.w};
    int d[4] = {D.x, D.y, D.z, D.w};
    const float4* XS4 = (const float4*)g_XS;

    #pragma unroll
    for (int j = 0; j < 4; j++) {
        if (kp & (1u << j)) {
            float4 a = __ldcg(&XS4[s[j] * 8 + sub]);
            red_add4(Y + d[j] * DD + sub * 4, a);
        }
    }
}

// out[i,:] = (Y2[i,:] * norm[i]) @ W^T    W is [32,32] row-major
__global__ void k_fc(const float4* __restrict__ Y4, const float* __restrict__ W,
                     float* __restrict__ out) {
    __shared__ float sW[DD * DD];
    int t = threadIdx.x;
    #pragma unroll
    for (int i = 0; i < 4; i++) sW[t + i * 256] = W[t + i * 256];
    __syncthreads();

    int node = blockIdx.x * blockDim.x + t;
    if (node >= NN) return;
    float nrm = g_norm[node];
    float y[DD];
    #pragma unroll
    for (int j = 0; j < 8; j++) {
        float4 v = Y4[node * 8 + j];
        y[j * 4 + 0] = v.x * nrm;
        y[j * 4 + 1] = v.y * nrm;
        y[j * 4 + 2] = v.z * nrm;
        y[j * 4 + 3] = v.w * nrm;
    }
    #pragma unroll
    for (int o = 0; o < DD; o += 4) {
        float4 acc = make_float4(0.f, 0.f, 0.f, 0.f);
        #pragma unroll
        for (int k = 0; k < DD; k++) {
            float yk = y[k];
            acc.x += yk * sW[(o + 0) * DD + k];
            acc.y += yk * sW[(o + 1) * DD + k];
            acc.z += yk * sW[(o + 2) * DD + k];
            acc.w += yk * sW[(o + 3) * DD + k];
        }
        *reinterpret_cast<float4*>(out + node * DD + o) = acc;
    }
}

// ---------------- launch ----------------

extern "C" void kernel_launch(void* const* d_in, const int* in_sizes, int n_in,
                              void* d_out, int out_size) {
    const float* F   = (const float*)d_in[0];
    const float* W   = (const float*)d_in[1];
    const int*   src = (const int*)d_in[2];
    const int*   dst = (const int*)d_in[3];
    float* out = (float*)d_out;

    const float4* F4  = (const float4*)F;
    const int4* src4  = (const int4*)src;
    const int4* dst4  = (const int4*)dst;

    void* p1; void* p2;
    cudaGetSymbolAddress(&p1, g_Y1);
    cudaGetSymbolAddress(&p2, g_Y2);
    float* Y1 = (float*)p1;
    float* Y2 = (float*)p2;

    const int TB = 256;
    const int gridN  = (NN + TB - 1) / TB;     // 391
    const int gridN8 = (NN * 8) / TB;          // 3125 (exact)
    const int gridE4 = (EG * 8) / TB;          // 12500 (exact)
    const int gridV4 = (EE / 4 + TB - 1) / TB; // 1563
    const int gridHS = 1184;

    k_init<<<gridN8, TB>>>();
    k_deg<<<gridV4, TB>>>(dst4);

    // ---- hop 1 ----
    k_prep1<<<gridN8, TB>>>(F4);               // NH(F), XS=F*norm, deg-norm
    k_cos<<<gridE4, TB>>>(src4, dst4);         // keys + pass0 hist + scan
    k_hs12<12><<<gridHS, TB>>>();              // bits [12:24)
    k_hs12<0><<<gridHS, TB>>>();               // bits [0:12)
    k_scatter<<<gridE4, TB>>>(Y1, src4, dst4); // kept-only, msg = XS[src]

    // ---- hop 2 (H2 = Y1*norm formed first: reference-exact rounding) ----
    k_prep2<<<gridN8, TB>>>((const float4*)Y1);  // NH(H2), XS=H2*norm, re-arm
    k_cos<<<gridE4, TB>>>(src4, dst4);
    k_hs12<12><<<gridHS, TB>>>();
    k_hs12<0><<<gridHS, TB>>>();
    k_scatter<<<gridE4, TB>>>(Y2, src4, dst4);

    // ---- final: out = (Y2 * norm) @ W^T ----
    k_fc<<<gridN, TB>>>((const float4*)Y2, W, out);
}